// round 16
// baseline (speedup 1.0000x reference)
#include <cuda_runtime.h>
#include <cuda_bf16.h>
#include <cstdint>

// ============================================================================
// ROUND 16 — mma.sync (baseline HMMA, bf16 hi/lo split) interior GEMM.
// tcgen05 is NOT available (harness targets plain sm_103). mma.sync +
// ldmatrix are sm_80+ baseline features and compile under compute_103.
// Verified I/O model: inputs dict-order element counts; output float32 concat
// [loss_pde, loss_bc, helm.real x N], out_size = 2 + N.
// ============================================================================

#define HID   128
#define N_INT 262144
#define N_BC  65536
#define PT    16                  // points per tile
#define MROWS 80                  // 5 vectors x 16 points
#define NT_I  (N_INT / PT)        // 16384 tiles (exact)
#define GI_TC 148
#define NBLK_B 296

#define PITCH_B  272              // bytes per bf16 row (136 elems)
#define PITCH_D  132              // floats per D row

// smem byte offsets
#define SM_BHI 0
#define SM_BLO 34816
#define SM_AHI 69632
#define SM_ALO 91392
#define SM_F   113152
// float offsets within F
#define F_D    0                  // 80*132 = 10560
#define F_A1   10560              // 16*129 = 2064
#define F_T1   12624              // 2064
#define F_W1R  14688              // 384
#define F_B1S  15072              // 128
#define F_C1S  15200              // 128
#define F_RED  15328              // 16*16 = 256
#define F_TOT  15584
#define SMEM_BYTES (SM_F + F_TOT * 4)   // 175488

__device__ float g_base1[HID];
__device__ float g_c1[HID];
__device__ float g_partial_pde[GI_TC];
__device__ float g_partial_bc[NBLK_B];

__device__ __forceinline__ float tanh_acc(float x) {
    float ax = fabsf(x);
    float e  = __expf(-2.0f * ax);
    float r  = (1.0f - e) / (1.0f + e);
    return (x < 0.0f) ? -r : r;
}

__device__ __forceinline__ uint32_t smem_u32(const void* p) {
    uint32_t a;
    asm("{ .reg .u64 t; cvta.to.shared.u64 t, %1; cvt.u32.u64 %0, t; }"
        : "=r"(a) : "l"(p));
    return a;
}

__device__ __forceinline__ void ldsm_x4(uint32_t& r0, uint32_t& r1,
                                        uint32_t& r2, uint32_t& r3, uint32_t a) {
    asm volatile("ldmatrix.sync.aligned.m8n8.x4.shared.b16 {%0,%1,%2,%3}, [%4];"
                 : "=r"(r0), "=r"(r1), "=r"(r2), "=r"(r3) : "r"(a));
}
__device__ __forceinline__ void ldsm_x2t(uint32_t& r0, uint32_t& r1, uint32_t a) {
    asm volatile("ldmatrix.sync.aligned.m8n8.x2.trans.shared.b16 {%0,%1}, [%2];"
                 : "=r"(r0), "=r"(r1) : "r"(a));
}
__device__ __forceinline__ void mma_bf16(float* c, uint32_t a0, uint32_t a1,
                                         uint32_t a2, uint32_t a3,
                                         uint32_t b0, uint32_t b1) {
    asm volatile(
        "mma.sync.aligned.m16n8k16.row.col.f32.bf16.bf16.f32 "
        "{%0,%1,%2,%3}, {%4,%5,%6,%7}, {%8,%9}, {%0,%1,%2,%3};"
        : "+f"(c[0]), "+f"(c[1]), "+f"(c[2]), "+f"(c[3])
        : "r"(a0), "r"(a1), "r"(a2), "r"(a3), "r"(b0), "r"(b1));
}

// FFMA2 helpers (boundary kernel)
__device__ __forceinline__ unsigned long long pack2(float lo, float hi) {
    unsigned long long r;
    asm("mov.b64 %0, {%1, %2};" : "=l"(r) : "f"(lo), "f"(hi));
    return r;
}
__device__ __forceinline__ void unpack2(unsigned long long v, float& lo, float& hi) {
    asm("mov.b64 {%0, %1}, %2;" : "=f"(lo), "=f"(hi) : "l"(v));
}
__device__ __forceinline__ void fma2(unsigned long long& d, unsigned long long a, unsigned long long b) {
    asm("fma.rn.f32x2 %0, %1, %2, %0;" : "+l"(d) : "l"(a), "l"(b));
}

// ---------------------------------------------------------------------------
__global__ void precompute_kernel(const float* __restrict__ latent,
                                  const float* __restrict__ W1,
                                  const float* __restrict__ b1) {
    int j = threadIdx.x;
    float b = b1[j];
    for (int i = 0; i < 64; ++i) b += latent[i] * W1[(3 + i) * HID + j];
    float c = 0.0f;
#pragma unroll
    for (int k = 0; k < 3; ++k) { float w = W1[k * HID + j]; c += w * w; }
    g_base1[j] = b;
    g_c1[j] = c;
}

// ---------------------------------------------------------------------------
// Interior: 256 threads / CTA, persistent over tiles of 16 points.
// ---------------------------------------------------------------------------
__global__ __launch_bounds__(256, 1) void interior_mma(
    const float* __restrict__ coords,
    const float* __restrict__ W1,
    const float* __restrict__ W2,
    const float* __restrict__ b2,
    const float* __restrict__ W3,
    const float* __restrict__ b3,
    float* __restrict__ outF, int helmMode, long long capF)
{
    extern __shared__ char smem[];
    const uint32_t sb = smem_u32(smem);
    float* F   = (float*)(smem + SM_F);
    float* D   = F + F_D;
    float* A1S = F + F_A1;
    float* T1S = F + F_T1;
    float* W1R = F + F_W1R;
    float* B1S = F + F_B1S;
    float* C1S = F + F_C1S;
    float* RED = F + F_RED;

    const int tid = threadIdx.x;
    const int w   = tid >> 5, lane = tid & 31;

    for (int i = tid; i < 384; i += 256) W1R[i] = W1[i];
    if (tid < 128) { B1S[tid] = g_base1[tid]; C1S[tid] = g_c1[tid]; }
    const int   je  = tid & 127;
    const float b2j = b2[je];
    const float w3r = W3[2 * je], w3i = W3[2 * je + 1];
    const float b30 = b3[0], b31 = b3[1];

    // Build B = W2 (k-major) bf16 hi/lo
    for (int idx = tid; idx < HID * HID; idx += 256) {
        int i = idx >> 7, j = idx & 127;
        float x = W2[idx];
        __nv_bfloat16 h = __float2bfloat16(x);
        float rem = x - __bfloat162float(h);
        __nv_bfloat16 l = __float2bfloat16(rem);
        uint32_t off = (uint32_t)i * PITCH_B + (uint32_t)j * 2;
        *(uint16_t*)(smem + SM_BHI + off) = __bfloat16_as_ushort(h);
        *(uint16_t*)(smem + SM_BLO + off) = __bfloat16_as_ushort(l);
    }
    __syncthreads();

    // ldmatrix base addresses
    const uint32_t aHiB = sb + SM_AHI + (uint32_t)(lane & 15) * PITCH_B + (uint32_t)(lane >> 4) * 16;
    const uint32_t aLoB = sb + SM_ALO + (uint32_t)(lane & 15) * PITCH_B + (uint32_t)(lane >> 4) * 16;
    const uint32_t bHiB = sb + SM_BHI + (uint32_t)(lane & 15) * PITCH_B + (uint32_t)(32 * w);
    const uint32_t bLoB = sb + SM_BLO + (uint32_t)(lane & 15) * PITCH_B + (uint32_t)(32 * w);

    float lossAcc = 0.0f;

    for (int tile = blockIdx.x; tile < NT_I; tile += gridDim.x) {
        const int p0 = tile * PT;
        __syncthreads();   // prev tile fully consumed

        // Phase 1: a1/t1 staging (16 x 128)
        for (int idx = tid; idx < PT * HID; idx += 256) {
            int p = idx >> 7, j = idx & 127;
            int gp = p0 + p;
            float x0 = coords[3 * gp], x1 = coords[3 * gp + 1], x2 = coords[3 * gp + 2];
            float z1 = B1S[j] + x0 * W1R[j] + x1 * W1R[HID + j] + x2 * W1R[2 * HID + j];
            float a1 = tanh_acc(z1);
            A1S[p * 129 + j] = a1;
            T1S[p * 129 + j] = 1.0f - a1 * a1;
        }
        __syncthreads();

        // Phase 2: build A rows (80 x 128) bf16 hi/lo
        for (int idx = tid; idx < MROWS * HID; idx += 256) {
            int r = idx >> 7, i = idx & 127;
            int p = r / 5, v = r - 5 * p;
            float a1 = A1S[p * 129 + i], t1 = T1S[p * 129 + i];
            float val;
            if (v == 0)      val = a1;
            else if (v == 4) val = -2.0f * a1 * t1 * C1S[i];
            else             val = t1 * W1R[(v - 1) * HID + i];
            __nv_bfloat16 h = __float2bfloat16(val);
            float rem = val - __bfloat162float(h);
            __nv_bfloat16 l = __float2bfloat16(rem);
            uint32_t off = (uint32_t)r * PITCH_B + (uint32_t)i * 2;
            *(uint16_t*)(smem + SM_AHI + off) = __bfloat16_as_ushort(h);
            *(uint16_t*)(smem + SM_ALO + off) = __bfloat16_as_ushort(l);
        }
        __syncthreads();

        // Phase 3: GEMM — AhBh + AlBh + AhBl, fp32 accum
        float acc[5][2][4];
#pragma unroll
        for (int m = 0; m < 5; ++m)
#pragma unroll
            for (int n = 0; n < 2; ++n)
#pragma unroll
                for (int q = 0; q < 4; ++q) acc[m][n][q] = 0.0f;

#pragma unroll
        for (int kt = 0; kt < 8; ++kt) {
            const uint32_t bRow = (uint32_t)(kt * 16) * PITCH_B;
            uint32_t bh00, bh01, bh10, bh11, bl00, bl01, bl10, bl11;
            ldsm_x2t(bh00, bh01, bHiB + bRow);
            ldsm_x2t(bh10, bh11, bHiB + bRow + 16);
            ldsm_x2t(bl00, bl01, bLoB + bRow);
            ldsm_x2t(bl10, bl11, bLoB + bRow + 16);
#pragma unroll
            for (int mt = 0; mt < 5; ++mt) {
                const uint32_t aOff = (uint32_t)(mt * 16) * PITCH_B + (uint32_t)(kt * 32);
                uint32_t a0, a1, a2, a3;
                ldsm_x4(a0, a1, a2, a3, aHiB + aOff);
                mma_bf16(acc[mt][0], a0, a1, a2, a3, bh00, bh01);
                mma_bf16(acc[mt][1], a0, a1, a2, a3, bh10, bh11);
                mma_bf16(acc[mt][0], a0, a1, a2, a3, bl00, bl01);
                mma_bf16(acc[mt][1], a0, a1, a2, a3, bl10, bl11);
                ldsm_x4(a0, a1, a2, a3, aLoB + aOff);
                mma_bf16(acc[mt][0], a0, a1, a2, a3, bh00, bh01);
                mma_bf16(acc[mt][1], a0, a1, a2, a3, bh10, bh11);
            }
        }

        // Phase 4: drain accumulators to D smem
        {
            const int r0 = lane >> 2, c0 = 2 * (lane & 3);
#pragma unroll
            for (int mt = 0; mt < 5; ++mt)
#pragma unroll
                for (int n2 = 0; n2 < 2; ++n2) {
                    int col = 16 * w + 8 * n2 + c0;
                    int row = 16 * mt + r0;
                    D[row * PITCH_D + col]           = acc[mt][n2][0];
                    D[row * PITCH_D + col + 1]       = acc[mt][n2][1];
                    D[(row + 8) * PITCH_D + col]     = acc[mt][n2][2];
                    D[(row + 8) * PITCH_D + col + 1] = acc[mt][n2][3];
                }
        }
        __syncthreads();

        // Phase 5: epilogue — thread = (half h, column j); 8 points per half
        {
            const int h = tid >> 7;
            const int wh = w & 3;   // warp within half
#pragma unroll
            for (int pp = 0; pp < 8; ++pp) {
                int p = 8 * h + pp;
                const float* Dp = D + (5 * p) * PITCH_D + je;
                float z2 = Dp[0];
                float v0 = Dp[PITCH_D], v1 = Dp[2 * PITCH_D];
                float v2 = Dp[3 * PITCH_D], wv = Dp[4 * PITCH_D];
                float a2 = tanh_acc(z2 + b2j);
                float t2 = 1.0f - a2 * a2;
                float sv = v0 * v0 + v1 * v1 + v2 * v2;
                float e  = t2 * (wv - 2.0f * a2 * sv);
                float q0 = a2 * w3r, q1 = a2 * w3i, q2 = e * w3r, q3 = e * w3i;
#pragma unroll
                for (int off = 16; off; off >>= 1) {
                    q0 += __shfl_xor_sync(0xffffffffu, q0, off);
                    q1 += __shfl_xor_sync(0xffffffffu, q1, off);
                    q2 += __shfl_xor_sync(0xffffffffu, q2, off);
                    q3 += __shfl_xor_sync(0xffffffffu, q3, off);
                }
                if (lane == 0) {
                    RED[p * 16 + 0 + wh]  = q0;
                    RED[p * 16 + 4 + wh]  = q1;
                    RED[p * 16 + 8 + wh]  = q2;
                    RED[p * 16 + 12 + wh] = q3;
                }
            }
        }
        __syncthreads();
        if (tid < PT) {
            int p = tid;
            float yre = RED[p*16+0] + RED[p*16+1] + RED[p*16+2] + RED[p*16+3];
            float yim = RED[p*16+4] + RED[p*16+5] + RED[p*16+6] + RED[p*16+7];
            float lre = RED[p*16+8] + RED[p*16+9] + RED[p*16+10] + RED[p*16+11];
            float lim = RED[p*16+12] + RED[p*16+13] + RED[p*16+14] + RED[p*16+15];
            float prr = yre + b30, pii = yim + b31;
            float hr = lre + 4.0f * prr;     // K^2 = 4 (real)
            float hi = lim + 4.0f * pii;
            int gp = p0 + p;
            if (helmMode == 1) {
                long long idx = 2LL + gp;
                if (idx < capF) outF[idx] = hr;
            } else if (helmMode == 2) {
                long long idx = 2LL + 2LL * gp;
                if (idx + 1 < capF) { outF[idx] = hr; outF[idx + 1] = hi; }
            }
            lossAcc += hr * hr + hi * hi;
        }
    }

    // Block loss reduction (only warp-0 lanes 0..15 carry nonzero)
    __syncthreads();
#pragma unroll
    for (int off = 16; off; off >>= 1)
        lossAcc += __shfl_xor_sync(0xffffffffu, lossAcc, off);
    if (lane == 0) RED[w] = lossAcc;
    __syncthreads();
    if (tid == 0) {
        float s = 0.f;
#pragma unroll
        for (int k = 0; k < 8; ++k) s += RED[k];
        g_partial_pde[blockIdx.x] = s;
    }
}

// ---------------------------------------------------------------------------
// Boundary: verified FFMA2 path (unchanged)
// ---------------------------------------------------------------------------
#define BPT 64
#define AP  129
#define NTILES_B (N_BC / BPT)

__global__ __launch_bounds__(256, 2) void boundary_kernel(
    const float* __restrict__ coords,
    const float* __restrict__ gt,
    const float* __restrict__ W1,
    const float* __restrict__ W2,
    const float* __restrict__ b2,
    const float* __restrict__ W3,
    const float* __restrict__ b3)
{
    extern __shared__ float smemf[];
    float* W2s    = smemf;
    float* Ab     = W2s + 16384;
    float* cs     = Ab + BPT * AP;
    float* W1r    = cs + 192;
    float* base1s = W1r + 384;
    float* b2s    = base1s + 128;
    float* W3s    = b2s + 128;
    float* red    = W3s + 256;

    const int tid  = threadIdx.x;
    const int g    = tid & 15;
    const int rr   = tid >> 4;
    const int lane = tid & 31;

    for (int idx = tid; idx < HID * HID; idx += 256) W2s[idx] = W2[idx];
    for (int idx = tid; idx < 384; idx += 256) W1r[idx] = W1[idx];
    if (tid < 128) { base1s[tid] = g_base1[tid]; b2s[tid] = b2[tid]; }
    if (tid < 256) W3s[tid] = W3[tid];
    const float b30 = b3[0], b31 = b3[1];
    __syncthreads();

    float accLoss = 0.0f;

    for (int tile = blockIdx.x; tile < NTILES_B; tile += gridDim.x) {
        const int p0 = tile * BPT;
        if (tid < BPT * 3) {
            int p = tid / 3, c = tid - p * 3;
            cs[tid] = coords[(p0 + p) * 3 + c];
        }
        __syncthreads();

        for (int r = tid; r < BPT * HID; r += 256) {
            int p = r >> 7, j = r & 127;
            float x0 = cs[p * 3], x1 = cs[p * 3 + 1], x2 = cs[p * 3 + 2];
            float z1 = base1s[j] + x0 * W1r[j] + x1 * W1r[128 + j] + x2 * W1r[256 + j];
            Ab[p * AP + j] = tanh_acc(z1);
        }
        __syncthreads();

        unsigned long long acc[4][4];
#pragma unroll
        for (int s = 0; s < 4; ++s)
#pragma unroll
            for (int t = 0; t < 4; ++t) acc[s][t] = 0ULL;

        const float* Wp = W2s + 2 * g;
#pragma unroll 4
        for (int i = 0; i < HID; ++i) {
            unsigned long long ds[4];
#pragma unroll
            for (int s = 0; s < 4; ++s) {
                float a = Ab[(rr + 16 * s) * AP + i];
                ds[s] = pack2(a, a);
            }
            const float* wr = Wp + i * HID;
#pragma unroll
            for (int t = 0; t < 4; ++t) {
                unsigned long long ww = *(const unsigned long long*)(wr + 32 * t);
                fma2(acc[0][t], ds[0], ww);
                fma2(acc[1][t], ds[1], ww);
                fma2(acc[2][t], ds[2], ww);
                fma2(acc[3][t], ds[3], ww);
            }
        }

#pragma unroll
        for (int s = 0; s < 4; ++s) {
            float yre = 0.f, yim = 0.f;
#pragma unroll
            for (int t = 0; t < 4; ++t) {
                float zl, zh;
                unpack2(acc[s][t], zl, zh);
                int j0 = 32 * t + 2 * g;
                float a2 = tanh_acc(zl + b2s[j0]);
                yre += a2 * W3s[2 * j0]; yim += a2 * W3s[2 * j0 + 1];
                int j1 = j0 + 1;
                float a2b = tanh_acc(zh + b2s[j1]);
                yre += a2b * W3s[2 * j1]; yim += a2b * W3s[2 * j1 + 1];
            }
#pragma unroll
            for (int off = 8; off >= 1; off >>= 1) {
                yre += __shfl_xor_sync(0xffffffffu, yre, off);
                yim += __shfl_xor_sync(0xffffffffu, yim, off);
            }
            if (g == 0) {
                int gp = p0 + rr + 16 * s;
                float dr = yre + b30 - gt[gp];
                float di = yim + b31;
                accLoss += dr * dr + di * di;
            }
        }
    }

#pragma unroll
    for (int off = 16; off >= 1; off >>= 1)
        accLoss += __shfl_xor_sync(0xffffffffu, accLoss, off);
    if (lane == 0) red[tid >> 5] = accLoss;
    __syncthreads();
    if (tid == 0) {
        float s = 0.f;
#pragma unroll
        for (int w = 0; w < 8; ++w) s += red[w];
        g_partial_bc[blockIdx.x] = s;
    }
}

// ---------------------------------------------------------------------------
__global__ void finalize_kernel(float* __restrict__ out, long long capF) {
    __shared__ float sp[256];
    __shared__ float sb2[256];
    float a = 0.f, b = 0.f;
    for (int i = threadIdx.x; i < GI_TC; i += 256) a += g_partial_pde[i];
    for (int i = threadIdx.x; i < NBLK_B; i += 256) b += g_partial_bc[i];
    sp[threadIdx.x] = a; sb2[threadIdx.x] = b;
    __syncthreads();
    for (int s = 128; s > 0; s >>= 1) {
        if (threadIdx.x < s) {
            sp[threadIdx.x] += sp[threadIdx.x + s];
            sb2[threadIdx.x] += sb2[threadIdx.x + s];
        }
        __syncthreads();
    }
    if (threadIdx.x == 0) {
        if (capF > 0) out[0] = sp[0] / (float)N_INT;
        if (capF > 1) out[1] = sb2[0] / (float)N_BC;
    }
}

__global__ void sentinel_kernel(float* __restrict__ out, float v) {
    if (threadIdx.x == 0) out[0] = v;
}

// ---------------------------------------------------------------------------
extern "C" void kernel_launch(void* const* d_in, const int* in_sizes, int n_in,
                              void* d_out, int out_size) {
    static const long long dictE[10] = {786432, 196608, 65536, 64, 8576, 128,
                                        16384, 128, 256, 2};
    bool ok = (n_in >= 10);
    if (ok)
        for (int i = 0; i < 10; ++i)
            if ((long long)in_sizes[i] != dictE[i]) { ok = false; break; }

    float* out = (float*)d_out;
    if (!ok) { sentinel_kernel<<<1, 32>>>(out, 1e4f); return; }

    const float* CI = (const float*)d_in[0];
    const float* CB = (const float*)d_in[1];
    const float* GT = (const float*)d_in[2];
    const float* LA = (const float*)d_in[3];
    const float* W1 = (const float*)d_in[4];
    const float* B1 = (const float*)d_in[5];
    const float* W2 = (const float*)d_in[6];
    const float* B2 = (const float*)d_in[7];
    const float* W3 = (const float*)d_in[8];
    const float* B3 = (const float*)d_in[9];

    const long long N = N_INT, os = out_size;
    int helmMode;
    if      (os == 2 + N)      helmMode = 1;   // verified model
    else if (os >= 2 + 2 * N)  helmMode = 2;
    else                       helmMode = 0;
    const long long capF = os;

    const size_t SHB = 25744 * sizeof(float);
    cudaFuncSetAttribute(interior_mma, cudaFuncAttributeMaxDynamicSharedMemorySize, SMEM_BYTES);
    cudaFuncSetAttribute(boundary_kernel, cudaFuncAttributeMaxDynamicSharedMemorySize, (int)SHB);

    precompute_kernel<<<1, HID>>>(LA, W1, B1);
    interior_mma<<<GI_TC, 256, SMEM_BYTES>>>(CI, W1, W2, B2, W3, B3, out, helmMode, capF);
    boundary_kernel<<<NBLK_B, 256, SHB>>>(CB, GT, W1, W2, B2, W3, B3);
    finalize_kernel<<<1, 256>>>(out, capF);
}